// round 14
// baseline (speedup 1.0000x reference)
#include <cuda_runtime.h>
#include <cuda_fp16.h>
#include <math.h>

#define FULLMASK 0xFFFFFFFFu

// ---------------- scratch (device globals; allocation-free) ----------------
// global pixel index space: scales concatenated, PIXOFF = {0,2097152,2621440,2752512,2785280}, total 2793472
__device__ __align__(16) __half2 g_amm[2793472];   // per-pixel (mean, max) interleaved
__device__ __align__(16) __half  g_sah[2793472];
__device__ float g_part[32 * 128 * 16];   // per-(b,cg) chunk partial sums
__device__ float g_catt[32 * 128];        // channel attention per (b, cg)

__device__ __forceinline__ float sigmoidf_(float x) {
    return 1.0f / (1.0f + __expf(-x));
}

// packed dual-fp32 FMA (SASS FFMA2; full fp32 precision per lane; PTX-only)
__device__ __forceinline__ void fma_f32x2(unsigned long long& d,
                                          unsigned long long a,
                                          unsigned long long b,
                                          unsigned long long c) {
    asm("fma.rn.f32x2 %0, %1, %2, %3;" : "=l"(d) : "l"(a), "l"(b), "l"(c));
}

// ---------------- Kernel 1: channel mean/max, single launch, constexpr dispatch ----------------
template<int C, int L2, int HW, int CHW, int POFF>
__device__ __forceinline__ void chanreduce_impl(const float* __restrict__ tp, int q)
{
    int p   = q * 4;                                   // pixel index within scale
    int pix = POFF + p;                                // global pixel index
    int b    = p >> L2;
    int hwid = p & (HW - 1);
    const float4* base = (const float4*)(tp + (size_t)b * CHW + hwid);
    constexpr int cs = HW / 4;                         // channel stride in float4s
    float4 v = __ldcs(base);                           // streaming: no reuse of t here
    float4 s = v, m = v;
#pragma unroll
    for (int c = 1; c < C; c++) {
        v = __ldcs(base + (size_t)c * cs);
        s.x += v.x; s.y += v.y; s.z += v.z; s.w += v.w;
        m.x = fmaxf(m.x, v.x); m.y = fmaxf(m.y, v.y);
        m.z = fmaxf(m.z, v.z); m.w = fmaxf(m.w, v.w);
    }
    constexpr float inv = 1.0f / (float)C;
    __half2 o0 = __floats2half2_rn(s.x * inv, m.x);
    __half2 o1 = __floats2half2_rn(s.y * inv, m.y);
    __half2 o2 = __floats2half2_rn(s.z * inv, m.z);
    __half2 o3 = __floats2half2_rn(s.w * inv, m.w);
    uint4 pk;
    pk.x = *(unsigned*)&o0; pk.y = *(unsigned*)&o1;
    pk.z = *(unsigned*)&o2; pk.w = *(unsigned*)&o3;
    *(uint4*)(g_amm + pix) = pk;                       // default store: re-read by k2 (L2-resident)
}

__global__ __launch_bounds__(256) void k_chanreduce(
    const float* __restrict__ t0, const float* __restrict__ t1,
    const float* __restrict__ t2, const float* __restrict__ t3,
    const float* __restrict__ t4)
{
    int q = blockIdx.x * 256 + threadIdx.x;            // quad index, exact 698368
    if (q < 524288)      chanreduce_impl<8,  16, 65536, 524288, 0>      (t0, q);
    else if (q < 655360) chanreduce_impl<16, 14, 16384, 262144, 2097152>(t1, q - 524288);
    else if (q < 688128) chanreduce_impl<24, 12, 4096,  98304,  2621440>(t2, q - 655360);
    else if (q < 696320) chanreduce_impl<32, 10, 1024,  32768,  2752512>(t3, q - 688128);
    else                 chanreduce_impl<48, 8,  256,   12288,  2785280>(t4, q - 696320);
}

// ---------------- Kernel 2: dilated 7x7 conv via packed f32x2 (mean,max lanes) ----------------
__global__ __launch_bounds__(256) void k_spconv(
    const float* __restrict__ spw, const float* __restrict__ spb)
{
    __shared__ __align__(16) float2 sxy[82 * 50];
    __shared__ unsigned long long wp2[49];
    int bx = blockIdx.x;
    int HD, hw, poff, tw, per;
    if (bx < 1024)      { HD = 256; hw = 65536; poff = 0;       tw = 8; per = 32; }
    else if (bx < 1280) { HD = 128; hw = 16384; poff = 2097152; tw = 4; per = 8;  bx -= 1024; }
    else if (bx < 1344) { HD = 64;  hw = 4096;  poff = 2621440; tw = 2; per = 2;  bx -= 1280; }
    else if (bx < 1376) { HD = 32;  hw = 1024;  poff = 2752512; tw = 1; per = 1;  bx -= 1344; }
    else                { HD = 16;  hw = 256;   poff = 2785280; tw = 1; per = 1;  bx -= 1376; }
    int b = bx / per, r = bx % per;
    int tyb = r / tw, txb = r % tw;
    int y0 = tyb * 64, x0 = txb * 32;
    int tid = threadIdx.x;
    if (tid < 49) {                                    // pack (mean_w, max_w) pairs
        float2 wpair = make_float2(spw[tid], spw[49 + tid]);
        wp2[tid] = *(unsigned long long*)&wpair;
    }
    int pb = poff + b * hw;
    for (int idx = tid; idx < 82 * 50; idx += 256) {
        int rr = idx / 50, cc = idx % 50;
        int gy = y0 - 9 + rr, gx = x0 - 9 + cc;
        float2 f = make_float2(0.f, 0.f);
        if ((unsigned)gy < (unsigned)HD && (unsigned)gx < (unsigned)HD)
            f = __half22float2(g_amm[pb + gy * HD + gx]);
        sxy[idx] = f;
    }
    __syncthreads();

    int ty = tid >> 5, tx = tid & 31;                  // warp = one ty row-group
    int gx = x0 + tx;
    unsigned long long acc2[8];
#pragma unroll
    for (int d = 0; d < 8; d++) acc2[d] = 0ull;
    int rbase = ty * 8;
    const unsigned long long* srow = (const unsigned long long*)sxy;
#pragma unroll
    for (int kw = 0; kw < 7; kw++) {
        int cc = tx + 3 * kw;
        unsigned long long cp[26];
#pragma unroll
        for (int j = 0; j < 26; j++)
            cp[j] = srow[(rbase + j) * 50 + cc];       // LDS.64 (mean,max) pair
#pragma unroll
        for (int kh = 0; kh < 7; kh++) {
            unsigned long long w2 = wp2[kh * 7 + kw];
#pragma unroll
            for (int d = 0; d < 8; d++)
                fma_f32x2(acc2[d], cp[d + 3 * kh], w2, acc2[d]);
        }
    }
    float bias = spb[0];
    if (gx < HD) {
#pragma unroll
        for (int d = 0; d < 8; d++) {
            int gy = y0 + rbase + d;
            if (gy < HD) {
                float2 a = *(float2*)&acc2[d];
                g_sah[pb + gy * HD + gx] = __float2half(sigmoidf_(a.x + a.y + bias));
            }
        }
    }
}

// ---------------- Kernel 3: pooled partials, chunk=8192, constexpr dispatch ----------------
template<int C, int HW, int CHW, int POFF, int CSTART>
__device__ __forceinline__ void pool_impl(const float* __restrict__ tp, int bx)
{
    constexpr int CHUNK = 8192;
    constexpr int CPP = (HW > CHUNK) ? (HW / CHUNK) : 1;   // chunks per channel
    constexpr int N   = (HW < CHUNK) ? HW : CHUNK;         // elements per chunk
    int b  = bx / (C * CPP);
    int r  = bx % (C * CPP);
    int c  = r / CPP;
    int ch = r % CPP;
    int start = ch * CHUNK;
    const float4* tb = (const float4*)(tp + (size_t)b * CHW + (size_t)c * HW + start);
    const __half* sp = g_sah + POFF + b * HW + start;
    int tid = threadIdx.x;
    float sumA = 0.f, sumB = 0.f;                      // two independent chains
#pragma unroll
    for (int i = tid, it = 0; i * 4 < N; i += 256, it++) {
        float4 tv = __ldcs(tb + i);                    // streaming t read
        uint2 sraw = *(const uint2*)(sp + 4 * i);      // sa: L2-resident (re-read by k_out)
        float2 f01 = __half22float2(*(half2*)&sraw.x);
        float2 f23 = __half22float2(*(half2*)&sraw.y);
        float pa  = tv.x * (1.f + f01.x) + tv.y * (1.f + f01.y);
        float pb2 = tv.z * (1.f + f23.x) + tv.w * (1.f + f23.y);
        if (it & 1) sumB += pa + pb2; else sumA += pa + pb2;
    }
    float sum = sumA + sumB;
#pragma unroll
    for (int o = 16; o; o >>= 1) sum += __shfl_down_sync(FULLMASK, sum, o);
    __shared__ float ws[8];
    if ((tid & 31) == 0) ws[tid >> 5] = sum;
    __syncthreads();
    if (tid == 0) {
        float tot = 0.f;
#pragma unroll
        for (int w2 = 0; w2 < 8; w2++) tot += ws[w2];
        g_part[(b * 128 + CSTART + c) * 16 + ch] = tot;
    }
}

__global__ __launch_bounds__(256) void k_pool(
    const float* __restrict__ t0, const float* __restrict__ t1,
    const float* __restrict__ t2, const float* __restrict__ t3,
    const float* __restrict__ t4)
{
    int bx = blockIdx.x;                               // exact 6400
    // grids: t0: 32*8*8=2048, t1: 32*16*2=1024, t2: 32*24=768, t3: 32*32=1024, t4: 32*48=1536
    if (bx < 2048)      pool_impl<8,  65536, 524288, 0,       0> (t0, bx);
    else if (bx < 3072) pool_impl<16, 16384, 262144, 2097152, 8> (t1, bx - 2048);
    else if (bx < 3840) pool_impl<24, 4096,  98304,  2621440, 24>(t2, bx - 3072);
    else if (bx < 4864) pool_impl<32, 1024,  32768,  2752512, 48>(t3, bx - 3840);
    else                pool_impl<48, 256,   12288,  2785280, 80>(t4, bx - 4864);
}

// ---------------- Kernel 4: 1D conv over pooled + per-scale FC + sigmoid -> catt ----------------
__global__ __launch_bounds__(128) void k_att(
    const float* __restrict__ c1d,
    const float* __restrict__ w0, const float* __restrict__ bb0,
    const float* __restrict__ w1, const float* __restrict__ bb1,
    const float* __restrict__ w2, const float* __restrict__ bb2,
    const float* __restrict__ w3, const float* __restrict__ bb3,
    const float* __restrict__ w4, const float* __restrict__ bb4)
{
    int b = blockIdx.x;
    int j = threadIdx.x;
    int cpp, hw, c_; const float* wp; const float* bp;
    if (j < 8)       { cpp = 8;  hw = 65536; wp = w0; bp = bb0; c_ = j;      }
    else if (j < 24) { cpp = 2;  hw = 16384; wp = w1; bp = bb1; c_ = j - 8;  }
    else if (j < 48) { cpp = 1;  hw = 4096;  wp = w2; bp = bb2; c_ = j - 24; }
    else if (j < 80) { cpp = 1;  hw = 1024;  wp = w3; bp = bb3; c_ = j - 48; }
    else             { cpp = 1;  hw = 256;   wp = w4; bp = bb4; c_ = j - 80; }

    const float4* wv = (const float4*)(wp + c_ * 128);
    float4 wpre[8];                                    // prefetch k=0..7 (hides one round trip)
#pragma unroll
    for (int k = 0; k < 8; k++) wpre[k] = wv[k];
    float bias = bp[c_];

    float pv = 0.f;
    for (int k = 0; k < cpp; k++) pv += g_part[(b * 128 + j) * 16 + k];
    pv /= (float)hw;
    __shared__ float psh[128];
    __shared__ __align__(16) float ash[128];
    psh[j] = pv;
    __syncthreads();
    float a = c1d[1] * psh[j];
    if (j > 0)   a += c1d[0] * psh[j - 1];
    if (j < 127) a += c1d[2] * psh[j + 1];
    ash[j] = a;
    __syncthreads();

    const float4* av = (const float4*)ash;
    float s0 = 0.f, s1 = 0.f, s2 = 0.f, s3 = 0.f;
#pragma unroll
    for (int k = 0; k < 8; k += 4) {                   // prefetched half
        float4 xa = av[k + 0], xb = av[k + 1], xc = av[k + 2], xd = av[k + 3];
        s0 += wpre[k+0].x * xa.x + wpre[k+0].y * xa.y + wpre[k+0].z * xa.z + wpre[k+0].w * xa.w;
        s1 += wpre[k+1].x * xb.x + wpre[k+1].y * xb.y + wpre[k+1].z * xb.z + wpre[k+1].w * xb.w;
        s2 += wpre[k+2].x * xc.x + wpre[k+2].y * xc.y + wpre[k+2].z * xc.z + wpre[k+2].w * xc.w;
        s3 += wpre[k+3].x * xd.x + wpre[k+3].y * xd.y + wpre[k+3].z * xd.z + wpre[k+3].w * xd.w;
    }
#pragma unroll
    for (int k = 8; k < 32; k += 4) {                  // streamed half (MLP ~24)
        float4 wa = wv[k + 0], wb = wv[k + 1], wc = wv[k + 2], wd = wv[k + 3];
        float4 xa = av[k + 0], xb = av[k + 1], xc = av[k + 2], xd = av[k + 3];
        s0 += wa.x * xa.x + wa.y * xa.y + wa.z * xa.z + wa.w * xa.w;
        s1 += wb.x * xb.x + wb.y * xb.y + wb.z * xb.z + wb.w * xb.w;
        s2 += wc.x * xc.x + wc.y * xc.y + wc.z * xc.z + wc.w * xc.w;
        s3 += wd.x * xd.x + wd.y * xd.y + wd.z * xd.z + wd.w * xd.w;
    }
    float dot = bias + ((s0 + s1) + (s2 + s3));
    g_catt[b * 128 + j] = sigmoidf_(dot);
}

// ---------------- Kernel 5: out = t * (catt + sa*(1+catt)) ----------------
__global__ __launch_bounds__(256) void k_out(
    const float* __restrict__ t0, const float* __restrict__ t1,
    const float* __restrict__ t2, const float* __restrict__ t3,
    const float* __restrict__ t4, float* __restrict__ out)
{
    int q = blockIdx.x * 256 + threadIdx.x;            // quad index, exact 7438336
    const float* tp; int chw, l2, hw, poff, cstart, toff4, sh, m3;
    if (q < 4194304)      { tp = t0; chw = 524288; l2 = 16; hw = 65536; poff = 0;       cstart = 0;  toff4 = 0;       sh = 19; m3 = 0; }
    else if (q < 6291456) { tp = t1; chw = 262144; l2 = 14; hw = 16384; poff = 2097152; cstart = 8;  toff4 = 4194304; sh = 18; m3 = 0; }
    else if (q < 7077888) { tp = t2; chw = 98304;  l2 = 12; hw = 4096;  poff = 2621440; cstart = 24; toff4 = 6291456; sh = 15; m3 = 1; }
    else if (q < 7340032) { tp = t3; chw = 32768;  l2 = 10; hw = 1024;  poff = 2752512; cstart = 48; toff4 = 7077888; sh = 15; m3 = 0; }
    else                  { tp = t4; chw = 12288;  l2 = 8;  hw = 256;   poff = 2785280; cstart = 80; toff4 = 7340032; sh = 12; m3 = 1; }
    int rem = (q - toff4) * 4;                         // element index within scale
    unsigned b = (unsigned)rem >> sh;                  // rem / chw via shift (+ /3 when m3)
    if (m3) b = __umulhi(b, 0xAAAAAAABu) >> 1;
    int r2   = rem - (int)b * chw;
    int c    = r2 >> l2;
    int hwid = r2 & (hw - 1);
    float catt = g_catt[b * 128 + cstart + c];
    const __half* sp = g_sah + poff + (int)b * hw + hwid;
    float2 f01 = __half22float2(*(const half2*)sp);
    float2 f23 = __half22float2(*(const half2*)(sp + 2));
    float4 tv = __ldcs((const float4*)(tp + rem));     // streaming t read
    float cp1 = 1.f + catt;
    float4 o;
    o.x = tv.x * (catt + f01.x * cp1);
    o.y = tv.y * (catt + f01.y * cp1);
    o.z = tv.z * (catt + f23.x * cp1);
    o.w = tv.w * (catt + f23.y * cp1);
    __stcs((float4*)out + q, o);                       // streaming write: never re-read
}

// ---------------- launch ----------------
extern "C" void kernel_launch(void* const* d_in, const int* in_sizes, int n_in,
                              void* d_out, int out_size)
{
    const float* t0  = (const float*)d_in[0];
    const float* t1  = (const float*)d_in[1];
    const float* t2  = (const float*)d_in[2];
    const float* t3  = (const float*)d_in[3];
    const float* t4  = (const float*)d_in[4];
    const float* spw = (const float*)d_in[5];
    const float* spb = (const float*)d_in[6];
    const float* c1d = (const float*)d_in[7];
    const float* w0  = (const float*)d_in[8];  const float* bb0 = (const float*)d_in[9];
    const float* w1  = (const float*)d_in[10]; const float* bb1 = (const float*)d_in[11];
    const float* w2  = (const float*)d_in[12]; const float* bb2 = (const float*)d_in[13];
    const float* w3  = (const float*)d_in[14]; const float* bb3 = (const float*)d_in[15];
    const float* w4  = (const float*)d_in[16]; const float* bb4 = (const float*)d_in[17];
    float* out = (float*)d_out;

    k_chanreduce<<<2728, 256>>>(t0, t1, t2, t3, t4);
    k_spconv   <<<1408, 256>>>(spw, spb);
    k_pool     <<<6400, 256>>>(t0, t1, t2, t3, t4);
    k_att      <<<32, 128>>>(c1d, w0, bb0, w1, bb1, w2, bb2, w3, bb3, w4, bb4);
    k_out      <<<29056, 256>>>(t0, t1, t2, t3, t4, out);
}

// round 15
// speedup vs baseline: 1.0026x; 1.0026x over previous
#include <cuda_runtime.h>
#include <cuda_fp16.h>
#include <math.h>

#define FULLMASK 0xFFFFFFFFu

// ---------------- scratch (device globals; allocation-free) ----------------
// global pixel index space: scales concatenated, PIXOFF = {0,2097152,2621440,2752512,2785280}, total 2793472
__device__ __align__(16) __half2 g_amm[2793472];   // per-pixel (mean, max) interleaved
__device__ __align__(16) __half  g_sah[2793472];
__device__ float g_part[32 * 128 * 16];   // per-(b,cg) chunk partial sums
__device__ float g_catt[32 * 128];        // channel attention per (b, cg)

__device__ __forceinline__ float sigmoidf_(float x) {
    return 1.0f / (1.0f + __expf(-x));
}

// packed dual-fp32 FMA (SASS FFMA2; full fp32 precision per lane; PTX-only)
__device__ __forceinline__ void fma_f32x2(unsigned long long& d,
                                          unsigned long long a,
                                          unsigned long long b,
                                          unsigned long long c) {
    asm("fma.rn.f32x2 %0, %1, %2, %3;" : "=l"(d) : "l"(a), "l"(b), "l"(c));
}

// ---------------- Kernel 1: channel mean/max, single launch, constexpr dispatch ----------------
// default-policy t loads: t lines linger in L2 for k_pool's re-read (t ~119MB vs L2 126MB)
template<int C, int L2, int HW, int CHW, int POFF>
__device__ __forceinline__ void chanreduce_impl(const float* __restrict__ tp, int q)
{
    int p   = q * 4;                                   // pixel index within scale
    int pix = POFF + p;                                // global pixel index
    int b    = p >> L2;
    int hwid = p & (HW - 1);
    const float4* base = (const float4*)(tp + (size_t)b * CHW + hwid);
    constexpr int cs = HW / 4;                         // channel stride in float4s
    float4 v = base[0];
    float4 s = v, m = v;
#pragma unroll
    for (int c = 1; c < C; c++) {
        v = base[(size_t)c * cs];
        s.x += v.x; s.y += v.y; s.z += v.z; s.w += v.w;
        m.x = fmaxf(m.x, v.x); m.y = fmaxf(m.y, v.y);
        m.z = fmaxf(m.z, v.z); m.w = fmaxf(m.w, v.w);
    }
    constexpr float inv = 1.0f / (float)C;
    __half2 o0 = __floats2half2_rn(s.x * inv, m.x);
    __half2 o1 = __floats2half2_rn(s.y * inv, m.y);
    __half2 o2 = __floats2half2_rn(s.z * inv, m.z);
    __half2 o3 = __floats2half2_rn(s.w * inv, m.w);
    uint4 pk;
    pk.x = *(unsigned*)&o0; pk.y = *(unsigned*)&o1;
    pk.z = *(unsigned*)&o2; pk.w = *(unsigned*)&o3;
    *(uint4*)(g_amm + pix) = pk;                       // re-read by k2 (L2-resident)
}

__global__ __launch_bounds__(256) void k_chanreduce(
    const float* __restrict__ t0, const float* __restrict__ t1,
    const float* __restrict__ t2, const float* __restrict__ t3,
    const float* __restrict__ t4)
{
    int q = blockIdx.x * 256 + threadIdx.x;            // quad index, exact 698368
    if (q < 524288)      chanreduce_impl<8,  16, 65536, 524288, 0>      (t0, q);
    else if (q < 655360) chanreduce_impl<16, 14, 16384, 262144, 2097152>(t1, q - 524288);
    else if (q < 688128) chanreduce_impl<24, 12, 4096,  98304,  2621440>(t2, q - 655360);
    else if (q < 696320) chanreduce_impl<32, 10, 1024,  32768,  2752512>(t3, q - 688128);
    else                 chanreduce_impl<48, 8,  256,   12288,  2785280>(t4, q - 696320);
}

// ---------------- Kernel 2: dilated 7x7 conv via packed f32x2 (mean,max lanes) ----------------
__global__ __launch_bounds__(256) void k_spconv(
    const float* __restrict__ spw, const float* __restrict__ spb)
{
    __shared__ __align__(16) float2 sxy[82 * 50];
    __shared__ unsigned long long wp2[49];
    int bx = blockIdx.x;
    int HD, hw, poff, tw, per;
    if (bx < 1024)      { HD = 256; hw = 65536; poff = 0;       tw = 8; per = 32; }
    else if (bx < 1280) { HD = 128; hw = 16384; poff = 2097152; tw = 4; per = 8;  bx -= 1024; }
    else if (bx < 1344) { HD = 64;  hw = 4096;  poff = 2621440; tw = 2; per = 2;  bx -= 1280; }
    else if (bx < 1376) { HD = 32;  hw = 1024;  poff = 2752512; tw = 1; per = 1;  bx -= 1344; }
    else                { HD = 16;  hw = 256;   poff = 2785280; tw = 1; per = 1;  bx -= 1376; }
    int b = bx / per, r = bx % per;
    int tyb = r / tw, txb = r % tw;
    int y0 = tyb * 64, x0 = txb * 32;
    int tid = threadIdx.x;
    if (tid < 49) {                                    // pack (mean_w, max_w) pairs
        float2 wpair = make_float2(spw[tid], spw[49 + tid]);
        wp2[tid] = *(unsigned long long*)&wpair;
    }
    int pb = poff + b * hw;
    for (int idx = tid; idx < 82 * 50; idx += 256) {
        int rr = idx / 50, cc = idx % 50;
        int gy = y0 - 9 + rr, gx = x0 - 9 + cc;
        float2 f = make_float2(0.f, 0.f);
        if ((unsigned)gy < (unsigned)HD && (unsigned)gx < (unsigned)HD)
            f = __half22float2(g_amm[pb + gy * HD + gx]);
        sxy[idx] = f;
    }
    __syncthreads();

    int ty = tid >> 5, tx = tid & 31;                  // warp = one ty row-group
    int gx = x0 + tx;
    unsigned long long acc2[8];
#pragma unroll
    for (int d = 0; d < 8; d++) acc2[d] = 0ull;
    int rbase = ty * 8;
    const unsigned long long* srow = (const unsigned long long*)sxy;
#pragma unroll
    for (int kw = 0; kw < 7; kw++) {
        int cc = tx + 3 * kw;
        unsigned long long cp[26];
#pragma unroll
        for (int j = 0; j < 26; j++)
            cp[j] = srow[(rbase + j) * 50 + cc];       // LDS.64 (mean,max) pair
#pragma unroll
        for (int kh = 0; kh < 7; kh++) {
            unsigned long long w2 = wp2[kh * 7 + kw];
#pragma unroll
            for (int d = 0; d < 8; d++)
                fma_f32x2(acc2[d], cp[d + 3 * kh], w2, acc2[d]);
        }
    }
    float bias = spb[0];
    if (gx < HD) {
#pragma unroll
        for (int d = 0; d < 8; d++) {
            int gy = y0 + rbase + d;
            if (gy < HD) {
                float2 a = *(float2*)&acc2[d];
                g_sah[pb + gy * HD + gx] = __float2half(sigmoidf_(a.x + a.y + bias));
            }
        }
    }
}

// ---------------- Kernel 3: pooled partials, chunk=4096, constexpr dispatch ----------------
// default-policy t loads: t lines linger in L2 for k_out's re-read
template<int C, int HW, int CHW, int POFF, int CSTART>
__device__ __forceinline__ void pool_impl(const float* __restrict__ tp, int bx)
{
    constexpr int CPP = (HW > 4096) ? (HW / 4096) : 1;   // chunks per channel
    constexpr int N   = (HW < 4096) ? HW : 4096;         // elements per chunk
    int b  = bx / (C * CPP);
    int r  = bx % (C * CPP);
    int c  = r / CPP;
    int ch = r % CPP;
    int start = ch * 4096;
    const float4* tb = (const float4*)(tp + (size_t)b * CHW + (size_t)c * HW + start);
    const __half* sp = g_sah + POFF + b * HW + start;
    int tid = threadIdx.x;
    float sumA = 0.f, sumB = 0.f;                      // two independent chains
#pragma unroll
    for (int i = tid, it = 0; i * 4 < N; i += 256, it++) {
        float4 tv = tb[i];
        uint2 sraw = *(const uint2*)(sp + 4 * i);      // sa: L2-resident (re-read by k_out)
        float2 f01 = __half22float2(*(half2*)&sraw.x);
        float2 f23 = __half22float2(*(half2*)&sraw.y);
        float pa  = tv.x * (1.f + f01.x) + tv.y * (1.f + f01.y);
        float pb2 = tv.z * (1.f + f23.x) + tv.w * (1.f + f23.y);
        if (it & 1) sumB += pa + pb2; else sumA += pa + pb2;
    }
    float sum = sumA + sumB;
#pragma unroll
    for (int o = 16; o; o >>= 1) sum += __shfl_down_sync(FULLMASK, sum, o);
    __shared__ float ws[8];
    if ((tid & 31) == 0) ws[tid >> 5] = sum;
    __syncthreads();
    if (tid == 0) {
        float tot = 0.f;
#pragma unroll
        for (int w2 = 0; w2 < 8; w2++) tot += ws[w2];
        g_part[(b * 128 + CSTART + c) * 16 + ch] = tot;
    }
}

__global__ __launch_bounds__(256) void k_pool(
    const float* __restrict__ t0, const float* __restrict__ t1,
    const float* __restrict__ t2, const float* __restrict__ t3,
    const float* __restrict__ t4)
{
    int bx = blockIdx.x;                               // exact 9472
    if (bx < 4096)      pool_impl<8,  65536, 524288, 0,       0> (t0, bx);
    else if (bx < 6144) pool_impl<16, 16384, 262144, 2097152, 8> (t1, bx - 4096);
    else if (bx < 6912) pool_impl<24, 4096,  98304,  2621440, 24>(t2, bx - 6144);
    else if (bx < 7936) pool_impl<32, 1024,  32768,  2752512, 48>(t3, bx - 6912);
    else                pool_impl<48, 256,   12288,  2785280, 80>(t4, bx - 7936);
}

// ---------------- Kernel 4: 1D conv over pooled + per-scale FC + sigmoid -> catt ----------------
__global__ __launch_bounds__(128) void k_att(
    const float* __restrict__ c1d,
    const float* __restrict__ w0, const float* __restrict__ bb0,
    const float* __restrict__ w1, const float* __restrict__ bb1,
    const float* __restrict__ w2, const float* __restrict__ bb2,
    const float* __restrict__ w3, const float* __restrict__ bb3,
    const float* __restrict__ w4, const float* __restrict__ bb4)
{
    int b = blockIdx.x;
    int j = threadIdx.x;
    int cpp, hw, c_; const float* wp; const float* bp;
    if (j < 8)       { cpp = 16; hw = 65536; wp = w0; bp = bb0; c_ = j;      }
    else if (j < 24) { cpp = 4;  hw = 16384; wp = w1; bp = bb1; c_ = j - 8;  }
    else if (j < 48) { cpp = 1;  hw = 4096;  wp = w2; bp = bb2; c_ = j - 24; }
    else if (j < 80) { cpp = 1;  hw = 1024;  wp = w3; bp = bb3; c_ = j - 48; }
    else             { cpp = 1;  hw = 256;   wp = w4; bp = bb4; c_ = j - 80; }

    const float4* wv = (const float4*)(wp + c_ * 128);
    float4 wpre[8];                                    // prefetch k=0..7 (hides one round trip)
#pragma unroll
    for (int k = 0; k < 8; k++) wpre[k] = wv[k];
    float bias = bp[c_];

    float pv = 0.f;
    for (int k = 0; k < cpp; k++) pv += g_part[(b * 128 + j) * 16 + k];
    pv /= (float)hw;
    __shared__ float psh[128];
    __shared__ __align__(16) float ash[128];
    psh[j] = pv;
    __syncthreads();
    float a = c1d[1] * psh[j];
    if (j > 0)   a += c1d[0] * psh[j - 1];
    if (j < 127) a += c1d[2] * psh[j + 1];
    ash[j] = a;
    __syncthreads();

    const float4* av = (const float4*)ash;
    float s0 = 0.f, s1 = 0.f, s2 = 0.f, s3 = 0.f;
#pragma unroll
    for (int k = 0; k < 8; k += 4) {                   // prefetched half
        float4 xa = av[k + 0], xb = av[k + 1], xc = av[k + 2], xd = av[k + 3];
        s0 += wpre[k+0].x * xa.x + wpre[k+0].y * xa.y + wpre[k+0].z * xa.z + wpre[k+0].w * xa.w;
        s1 += wpre[k+1].x * xb.x + wpre[k+1].y * xb.y + wpre[k+1].z * xb.z + wpre[k+1].w * xb.w;
        s2 += wpre[k+2].x * xc.x + wpre[k+2].y * xc.y + wpre[k+2].z * xc.z + wpre[k+2].w * xc.w;
        s3 += wpre[k+3].x * xd.x + wpre[k+3].y * xd.y + wpre[k+3].z * xd.z + wpre[k+3].w * xd.w;
    }
#pragma unroll
    for (int k = 8; k < 32; k += 4) {                  // streamed half (MLP ~24)
        float4 wa = wv[k + 0], wb = wv[k + 1], wc = wv[k + 2], wd = wv[k + 3];
        float4 xa = av[k + 0], xb = av[k + 1], xc = av[k + 2], xd = av[k + 3];
        s0 += wa.x * xa.x + wa.y * xa.y + wa.z * xa.z + wa.w * xa.w;
        s1 += wb.x * xb.x + wb.y * xb.y + wb.z * xb.z + wb.w * xb.w;
        s2 += wc.x * xc.x + wc.y * xc.y + wc.z * xc.z + wc.w * xc.w;
        s3 += wd.x * xd.x + wd.y * xd.y + wd.z * xd.z + wd.w * xd.w;
    }
    float dot = bias + ((s0 + s1) + (s2 + s3));
    g_catt[b * 128 + j] = sigmoidf_(dot);
}

// ---------------- Kernel 5: out = t * (catt + sa*(1+catt)) ----------------
__global__ __launch_bounds__(256) void k_out(
    const float* __restrict__ t0, const float* __restrict__ t1,
    const float* __restrict__ t2, const float* __restrict__ t3,
    const float* __restrict__ t4, float* __restrict__ out)
{
    int q = blockIdx.x * 256 + threadIdx.x;            // quad index, exact 7438336
    const float* tp; int chw, l2, hw, poff, cstart, toff4, sh, m3;
    if (q < 4194304)      { tp = t0; chw = 524288; l2 = 16; hw = 65536; poff = 0;       cstart = 0;  toff4 = 0;       sh = 19; m3 = 0; }
    else if (q < 6291456) { tp = t1; chw = 262144; l2 = 14; hw = 16384; poff = 2097152; cstart = 8;  toff4 = 4194304; sh = 18; m3 = 0; }
    else if (q < 7077888) { tp = t2; chw = 98304;  l2 = 12; hw = 4096;  poff = 2621440; cstart = 24; toff4 = 6291456; sh = 15; m3 = 1; }
    else if (q < 7340032) { tp = t3; chw = 32768;  l2 = 10; hw = 1024;  poff = 2752512; cstart = 48; toff4 = 7077888; sh = 15; m3 = 0; }
    else                  { tp = t4; chw = 12288;  l2 = 8;  hw = 256;   poff = 2785280; cstart = 80; toff4 = 7340032; sh = 12; m3 = 1; }
    int rem = (q - toff4) * 4;                         // element index within scale
    unsigned b = (unsigned)rem >> sh;                  // rem / chw via shift (+ /3 when m3)
    if (m3) b = __umulhi(b, 0xAAAAAAABu) >> 1;
    int r2   = rem - (int)b * chw;
    int c    = r2 >> l2;
    int hwid = r2 & (hw - 1);
    float catt = g_catt[b * 128 + cstart + c];
    const __half* sp = g_sah + poff + (int)b * hw + hwid;
    float2 f01 = __half22float2(*(const half2*)sp);
    float2 f23 = __half22float2(*(const half2*)(sp + 2));
    float4 tv = __ldcs((const float4*)(tp + rem));     // last reader of t: evict-first
    float cp1 = 1.f + catt;
    float4 o;
    o.x = tv.x * (catt + f01.x * cp1);
    o.y = tv.y * (catt + f01.y * cp1);
    o.z = tv.z * (catt + f23.x * cp1);
    o.w = tv.w * (catt + f23.y * cp1);
    __stcs((float4*)out + q, o);                       // streaming write: never re-read
}

// ---------------- launch ----------------
extern "C" void kernel_launch(void* const* d_in, const int* in_sizes, int n_in,
                              void* d_out, int out_size)
{
    const float* t0  = (const float*)d_in[0];
    const float* t1  = (const float*)d_in[1];
    const float* t2  = (const float*)d_in[2];
    const float* t3  = (const float*)d_in[3];
    const float* t4  = (const float*)d_in[4];
    const float* spw = (const float*)d_in[5];
    const float* spb = (const float*)d_in[6];
    const float* c1d = (const float*)d_in[7];
    const float* w0  = (const float*)d_in[8];  const float* bb0 = (const float*)d_in[9];
    const float* w1  = (const float*)d_in[10]; const float* bb1 = (const float*)d_in[11];
    const float* w2  = (const float*)d_in[12]; const float* bb2 = (const float*)d_in[13];
    const float* w3  = (const float*)d_in[14]; const float* bb3 = (const float*)d_in[15];
    const float* w4  = (const float*)d_in[16]; const float* bb4 = (const float*)d_in[17];
    float* out = (float*)d_out;

    k_chanreduce<<<2728, 256>>>(t0, t1, t2, t3, t4);
    k_spconv   <<<1408, 256>>>(spw, spb);
    k_pool     <<<9472, 256>>>(t0, t1, t2, t3, t4);
    k_att      <<<32, 128>>>(c1d, w0, bb0, w1, bb1, w2, bb2, w3, bb3, w4, bb4);
    k_out      <<<29056, 256>>>(t0, t1, t2, t3, t4, out);
}